// round 7
// baseline (speedup 1.0000x reference)
#include <cuda_runtime.h>
#include <cstdint>

// Problem dims
#define M_TOTAL 8192
#define N_TOTAL 4096
#define K_TOTAL 4096

// GEMM tiling
#define TILE_M 128
#define TILE_N 128
#define KC 64                       // int8 elems per K-chunk (64 B per row)
#define NST 4                       // pipeline stages
#define NCHUNK (K_TOTAL / KC)       // 64
#define THREADS 256                 // 8 warps: 2 (M) x 4 (N), warp tile 64x32

#define A_TILE_BYTES (TILE_M * KC)              // 8192
#define B_TILE_BYTES (TILE_N * KC)              // 8192
#define STAGE_BYTES (A_TILE_BYTES + B_TILE_BYTES)   // 16384
#define SMEM_TOTAL (NST * STAGE_BYTES)              // 65536

// Scratch (device globals: allocation-free per harness rules)
__device__ int8_t g_xq[(size_t)M_TOTAL * K_TOTAL];   // 32 MB
__device__ int8_t g_wb[(size_t)N_TOTAL * K_TOTAL];   // 16 MB

// ---------------------------------------------------------------- PTX helpers
static __device__ __forceinline__ uint32_t smem_u32(const void* p) {
    uint32_t a;
    asm("{ .reg .u64 t; cvta.to.shared.u64 t, %1; cvt.u32.u64 %0, t; }"
        : "=r"(a) : "l"(p));
    return a;
}
static __device__ __forceinline__ void cp_async16(uint32_t saddr, const void* gptr) {
    asm volatile("cp.async.cg.shared.global [%0], [%1], 16;" :: "r"(saddr), "l"(gptr) : "memory");
}
#define CP_COMMIT() asm volatile("cp.async.commit_group;" ::: "memory")
#define CP_WAIT(n)  asm volatile("cp.async.wait_group %0;" :: "n"(n) : "memory")

static __device__ __forceinline__ void ldsm_x4(uint32_t r[4], uint32_t addr) {
    asm volatile("ldmatrix.sync.aligned.m8n8.x4.shared.b16 {%0,%1,%2,%3}, [%4];"
                 : "=r"(r[0]), "=r"(r[1]), "=r"(r[2]), "=r"(r[3]) : "r"(addr));
}
static __device__ __forceinline__ void mma_s8(int c[4], const uint32_t a[4],
                                              uint32_t b0, uint32_t b1) {
    asm volatile(
        "mma.sync.aligned.m16n8k32.row.col.s32.s8.s8.s32 "
        "{%0,%1,%2,%3}, {%4,%5,%6,%7}, {%8,%9}, {%0,%1,%2,%3};"
        : "+r"(c[0]), "+r"(c[1]), "+r"(c[2]), "+r"(c[3])
        : "r"(a[0]), "r"(a[1]), "r"(a[2]), "r"(a[3]), "r"(b0), "r"(b1));
}

static __device__ __forceinline__ int pack4(float q0, float q1, float q2, float q3) {
    int v0 = (int)q0, v1 = (int)q1, v2 = (int)q2, v3 = (int)q3;
    return (v0 & 0xFF) | ((v1 & 0xFF) << 8) | ((v2 & 0xFF) << 16) | (v3 << 24);
}

// ---------------------------------------------------------------- pre-kernels
// x fp32 -> int8 (static quant: clamp(round(x / input_scale)))
__global__ void quant_x_kernel(const float* __restrict__ x,
                               const float* __restrict__ input_scale) {
    size_t i = ((size_t)blockIdx.x * blockDim.x + threadIdx.x) * 16;
    float s = __ldg(input_scale);
    int o[4];
    #pragma unroll
    for (int j = 0; j < 4; j++) {
        float4 a = *reinterpret_cast<const float4*>(x + i + j * 4);
        float q0 = fminf(fmaxf(rintf(__fdiv_rn(a.x, s)), -128.f), 127.f);
        float q1 = fminf(fmaxf(rintf(__fdiv_rn(a.y, s)), -128.f), 127.f);
        float q2 = fminf(fmaxf(rintf(__fdiv_rn(a.z, s)), -128.f), 127.f);
        float q3 = fminf(fmaxf(rintf(__fdiv_rn(a.w, s)), -128.f), 127.f);
        o[j] = pack4(q0, q1, q2, q3);
    }
    *reinterpret_cast<int4*>(&g_xq[i]) = make_int4(o[0], o[1], o[2], o[3]);
}

// weight int32 (int8 range) -> int8: exact truncation of low byte
__global__ void conv_w_kernel(const int* __restrict__ w) {
    size_t i = ((size_t)blockIdx.x * blockDim.x + threadIdx.x) * 16;
    int o[4];
    #pragma unroll
    for (int j = 0; j < 4; j++) {
        int4 a = *reinterpret_cast<const int4*>(w + i + j * 4);
        o[j] = (a.x & 0xFF) | ((a.y & 0xFF) << 8) | ((a.z & 0xFF) << 16) | (a.w << 24);
    }
    *reinterpret_cast<int4*>(&g_wb[i]) = make_int4(o[0], o[1], o[2], o[3]);
}

// ---------------------------------------------------------------- GEMM kernel
// Smem tile layout: 128 rows x 64 bytes; 16B segment s of row r stored at
//   r*64 + ((s ^ ((r>>1)&3)) * 16)
// -> conflict-free ldmatrix (even rows hit banks 0-15, odd rows 16-31, each once).
__global__ __launch_bounds__(THREADS, 2)
void gemm_kernel(float* __restrict__ out,
                 const float* __restrict__ scale,
                 const float* __restrict__ input_scale) {
    extern __shared__ char smem[];
    uint32_t sb = smem_u32(smem);
    int tid = threadIdx.x;
    int wid = tid >> 5;
    int lane = tid & 31;
    int tm = blockIdx.x;   // 0..63
    int tn = blockIdx.y;   // 0..31

    int warp_m = wid & 1;        // 0..1 -> 64-row slab
    int warp_n = wid >> 1;       // 0..3 -> 32-col slab

    const int8_t* Abase = g_xq + (size_t)(tm * TILE_M) * K_TOTAL;
    const int8_t* Bbase = g_wb + (size_t)(tn * TILE_N) * K_TOTAL;

    // cp.async mapping: chunk c in [0,512): row = c>>2, seg = c&3
    int c0 = tid, c1 = tid + 256;
    int r0 = c0 >> 2, s0 = c0 & 3, r1 = c1 >> 2, s1 = c1 & 3;
    uint32_t dA0 = r0 * 64 + ((s0 ^ ((r0 >> 1) & 3)) << 4);
    uint32_t dA1 = r1 * 64 + ((s1 ^ ((r1 >> 1) & 3)) << 4);

    // ldmatrix per-lane addressing
    int t = lane >> 3, rr = lane & 7;
    // A: addr groups -> {rows0-7,k0-15},{rows8-15,k0-15},{rows0-7,k16-31},{rows8-15,k16-31}
    int khA = t >> 1;
    int mA[4], xorA[4];
    #pragma unroll
    for (int mi = 0; mi < 4; mi++) {
        mA[mi] = warp_m * 64 + mi * 16 + (t & 1) * 8 + rr;
        xorA[mi] = (mA[mi] >> 1) & 3;
    }
    // B: addr groups -> {n0-7,k0},{n0-7,k1},{n8-15,k0},{n8-15,k1}
    int khB = t & 1;
    int nB[2], xorB[2];
    #pragma unroll
    for (int ni2 = 0; ni2 < 2; ni2++) {
        nB[ni2] = warp_n * 32 + ni2 * 16 + (t >> 1) * 8 + rr;
        xorB[ni2] = (nB[ni2] >> 1) & 3;
    }

    int acc[4][4][4];
    #pragma unroll
    for (int mi = 0; mi < 4; mi++)
        #pragma unroll
        for (int ni = 0; ni < 4; ni++)
            #pragma unroll
            for (int q = 0; q < 4; q++) acc[mi][ni][q] = 0;

    // ---- prologue: issue NST-1 stages
    #pragma unroll
    for (int s = 0; s < NST - 1; s++) {
        uint32_t sa = sb + s * STAGE_BYTES;
        uint32_t sbb = sa + A_TILE_BYTES;
        const int8_t* Ak = Abase + s * KC;
        const int8_t* Bk = Bbase + s * KC;
        cp_async16(sa + dA0, Ak + (size_t)r0 * K_TOTAL + s0 * 16);
        cp_async16(sa + dA1, Ak + (size_t)r1 * K_TOTAL + s1 * 16);
        cp_async16(sbb + dA0, Bk + (size_t)r0 * K_TOTAL + s0 * 16);
        cp_async16(sbb + dA1, Bk + (size_t)r1 * K_TOTAL + s1 * 16);
        CP_COMMIT();
    }

    // ---- mainloop
    for (int j = 0; j < NCHUNK; j++) {
        CP_WAIT(NST - 2);
        __syncthreads();

        uint32_t sa = sb + (j & (NST - 1)) * STAGE_BYTES;
        uint32_t sbb = sa + A_TILE_BYTES;

        #pragma unroll
        for (int ks = 0; ks < 2; ks++) {
            uint32_t af[4][4];
            #pragma unroll
            for (int mi = 0; mi < 4; mi++)
                ldsm_x4(af[mi], sa + mA[mi] * 64 + (((2 * ks + khA) ^ xorA[mi]) << 4));
            uint32_t bf[4][2];
            #pragma unroll
            for (int ni2 = 0; ni2 < 2; ni2++) {
                uint32_t r[4];
                ldsm_x4(r, sbb + nB[ni2] * 64 + (((2 * ks + khB) ^ xorB[ni2]) << 4));
                bf[ni2 * 2][0] = r[0]; bf[ni2 * 2][1] = r[1];
                bf[ni2 * 2 + 1][0] = r[2]; bf[ni2 * 2 + 1][1] = r[3];
            }
            #pragma unroll
            for (int mi = 0; mi < 4; mi++)
                #pragma unroll
                for (int ni = 0; ni < 4; ni++)
                    mma_s8(acc[mi][ni], af[mi], bf[ni][0], bf[ni][1]);
        }

        // issue stage j+NST-1 (overwrites buffer (j-1)%NST: safe after the sync)
        int kn = j + NST - 1;
        if (kn < NCHUNK) {
            uint32_t na = sb + (kn & (NST - 1)) * STAGE_BYTES;
            uint32_t nb = na + A_TILE_BYTES;
            const int8_t* Ak = Abase + kn * KC;
            const int8_t* Bk = Bbase + kn * KC;
            cp_async16(na + dA0, Ak + (size_t)r0 * K_TOTAL + s0 * 16);
            cp_async16(na + dA1, Ak + (size_t)r1 * K_TOTAL + s1 * 16);
            cp_async16(nb + dA0, Bk + (size_t)r0 * K_TOTAL + s0 * 16);
            cp_async16(nb + dA1, Bk + (size_t)r1 * K_TOTAL + s1 * 16);
        }
        CP_COMMIT();
    }

    // ---- epilogue: scale int32 accumulators, write fp32
    float cs = __ldg(scale) * __ldg(input_scale);
    int rbase = tm * TILE_M + warp_m * 64 + (lane >> 2);
    int cbase = tn * TILE_N + warp_n * 32 + (lane & 3) * 2;
    #pragma unroll
    for (int mi = 0; mi < 4; mi++) {
        #pragma unroll
        for (int ni = 0; ni < 4; ni++) {
            int r = rbase + mi * 16;
            int c = cbase + ni * 8;
            float2 v0, v1;
            v0.x = (float)acc[mi][ni][0] * cs;
            v0.y = (float)acc[mi][ni][1] * cs;
            v1.x = (float)acc[mi][ni][2] * cs;
            v1.y = (float)acc[mi][ni][3] * cs;
            *reinterpret_cast<float2*>(out + (size_t)r * N_TOTAL + c) = v0;
            *reinterpret_cast<float2*>(out + (size_t)(r + 8) * N_TOTAL + c) = v1;
        }
    }
}

// ---------------------------------------------------------------- launch
extern "C" void kernel_launch(void* const* d_in, const int* in_sizes, int n_in,
                              void* d_out, int out_size) {
    const float* x           = (const float*)d_in[0];
    const int*   weight      = (const int*)d_in[1];
    const float* scale       = (const float*)d_in[2];
    const float* input_scale = (const float*)d_in[3];
    float* out = (float*)d_out;

    // 1) quantize x -> int8 (exact)
    {
        size_t n = (size_t)M_TOTAL * K_TOTAL;           // 33554432
        int blocks = (int)(n / 16 / 256);               // 8192
        quant_x_kernel<<<blocks, 256>>>(x, input_scale);
    }
    // 2) weight int32 -> int8 (exact truncation)
    {
        size_t n = (size_t)N_TOTAL * K_TOTAL;           // 16777216
        int blocks = (int)(n / 16 / 256);               // 4096
        conv_w_kernel<<<blocks, 256>>>(weight);
    }
    // 3) IMMA int8 GEMM, s32 accumulate, fused fp32 scale epilogue
    {
        cudaFuncSetAttribute(gemm_kernel,
                             cudaFuncAttributeMaxDynamicSharedMemorySize, SMEM_TOTAL);
        dim3 grid(M_TOTAL / TILE_M, N_TOTAL / TILE_N);  // 64 x 32
        gemm_kernel<<<grid, THREADS, SMEM_TOTAL>>>(out, scale, input_scale);
    }
}